// round 10
// baseline (speedup 1.0000x reference)
#include <cuda_runtime.h>
#include <cuda_fp16.h>
#include <math.h>

#define NN 100000
#define NE 3200000
#define IN_FEAT 512
#define HID 16
#define NC 7
#define MAXNB 512   // max node-blocks (ceil(100000/256)=391)

// ---------------- scratch (device globals; no allocation allowed) -------------
__device__ int   g_is64;
__device__ int   g_cnt [NN];      // in-degree (edges only)
__device__ int   g_rows[NN];      // CSR row starts
__device__ int   g_cur [NN];      // fill cursors
__device__ int   g_blk_agg [MAXNB];
__device__ int   g_blk_inc [MAXNB];
__device__ int   g_blk_flag[MAXNB];   // 0=none 1=agg 2=inclusive
__device__ int   g_csr [NE];      // src per CSR slot
__device__ float g_dinv[NN];
__device__ uint4 g_hnh [NN * 2];  // h1*dinv, 16 x fp16 per node (32B)
__device__ uint4 g_h2h [NN];      // h2*dinv, 7 x fp16 + pad (16B)

// ---------------- helpers ------------------------------------------------------
__device__ __forceinline__ unsigned long long pack2(float a, float b) {
    unsigned long long r;
    asm("mov.b64 %0, {%1,%2};" : "=l"(r) : "f"(a), "f"(b));
    return r;
}
__device__ __forceinline__ unsigned long long add2(unsigned long long a,
                                                   unsigned long long b) {
    unsigned long long d;
    asm("add.rn.f32x2 %0, %1, %2;" : "=l"(d) : "l"(a), "l"(b));
    return d;
}
__device__ __forceinline__ float2 unpack2(unsigned long long v) {
    float2 f;
    asm("mov.b64 {%0,%1}, %2;" : "=f"(f.x), "=f"(f.y) : "l"(v));
    return f;
}
__device__ __forceinline__ void add8(float* a, uint4 v) {
    float2 f0 = __half22float2(*(__half2*)&v.x);
    float2 f1 = __half22float2(*(__half2*)&v.y);
    float2 f2 = __half22float2(*(__half2*)&v.z);
    float2 f3 = __half22float2(*(__half2*)&v.w);
    a[0] += f0.x; a[1] += f0.y; a[2] += f1.x; a[3] += f1.y;
    a[4] += f2.x; a[5] += f2.y; a[6] += f3.x; a[7] += f3.y;
}

// ---------------- zero counts + scan flags + dtype detect ----------------------
__global__ void k_zero_detect(const int* __restrict__ ei, int n) {
    int i = blockIdx.x * blockDim.x + threadIdx.x;
    if (i < n) g_cnt[i] = 0;
    if (i < MAXNB) { g_blk_flag[i] = 0; g_blk_agg[i] = 0; g_blk_inc[i] = 0; }
    if (blockIdx.x == 0 && threadIdx.x == 0) {
        int nz = 0;
#pragma unroll
        for (int k = 1; k < 64; k += 2) nz |= ei[k];   // int64 high words == 0
        g_is64 = (nz == 0) ? 1 : 0;
    }
}

// ---------------- degree count: 4 edges/thread (MLP=4) -------------------------
__global__ void k_count(const void* __restrict__ ei, int E) {
    int t = blockIdx.x * blockDim.x + threadIdx.x;
    int e = t * 4;
    if (e >= E) return;
    int d[4];
    int m = E - e;   // >=1
    if (g_is64) {
        const long long* p = (const long long*)ei + E;
        if (m >= 4) {
            longlong2 v0 = ((const longlong2*)(p + e))[0];
            longlong2 v1 = ((const longlong2*)(p + e))[1];
            d[0] = (int)v0.x; d[1] = (int)v0.y; d[2] = (int)v1.x; d[3] = (int)v1.y;
        } else {
            for (int k = 0; k < 4; k++) d[k] = (k < m) ? (int)p[e + k] : -1;
        }
    } else {
        const int* p = (const int*)ei + E;
        if (m >= 4) {
            int4 v = *(const int4*)(p + e);
            d[0] = v.x; d[1] = v.y; d[2] = v.z; d[3] = v.w;
        } else {
            for (int k = 0; k < 4; k++) d[k] = (k < m) ? p[e + k] : -1;
        }
    }
#pragma unroll
    for (int k = 0; k < 4; k++)
        if (d[k] >= 0) atomicAdd(&g_cnt[d[k]], 1);
}

// ---------------- fused dinv + full exclusive scan (decoupled lookback) --------
__global__ void __launch_bounds__(256) k_csr_offsets(int n) {
    __shared__ int sh[256];
    __shared__ int s_excl;
    int b = blockIdx.x, t = threadIdx.x;
    int i = b * 256 + t;
    int c = (i < n) ? g_cnt[i] : 0;
    if (i < n) g_dinv[i] = rsqrtf((float)(c + 1));

    sh[t] = c;
    __syncthreads();
#pragma unroll
    for (int off = 1; off < 256; off <<= 1) {
        int v = (t >= off) ? sh[t - off] : 0;
        __syncthreads();
        sh[t] += v;
        __syncthreads();
    }

    if (t == 255) {
        if (b == 0) {
            g_blk_inc[0] = sh[255];
            __threadfence();
            atomicExch(&g_blk_flag[0], 2);
        } else {
            g_blk_agg[b] = sh[255];
            __threadfence();
            atomicExch(&g_blk_flag[b], 1);
        }
    }

    if (b == 0) {
        if (t == 0) s_excl = 0;
    } else if (t < 32) {
        int lane = t;
        int run = 0, pos = b - 1, done = 0, excl = 0;
        while (!done) {
            int idx = pos - lane;
            int f = (idx >= 0) ? *(volatile int*)&g_blk_flag[idx] : 2;
            unsigned b2 = __ballot_sync(0xffffffffu, f >= 2);
            unsigned b1 = __ballot_sync(0xffffffffu, f >= 1);
            if (b2) {
                int k = __ffs(b2) - 1;
                unsigned need = (k == 0) ? 0u : ((1u << k) - 1u);
                if ((b1 & need) == need) {
                    int contrib = 0;
                    if (lane < k)       contrib = *(volatile int*)&g_blk_agg[idx];
                    else if (lane == k) contrib = (idx >= 0)
                                                ? *(volatile int*)&g_blk_inc[idx] : 0;
#pragma unroll
                    for (int o = 16; o > 0; o >>= 1)
                        contrib += __shfl_xor_sync(0xffffffffu, contrib, o);
                    excl = run + contrib;
                    done = 1;
                }
            } else if (b1 == 0xffffffffu) {
                int contrib = *(volatile int*)&g_blk_agg[idx];
#pragma unroll
                for (int o = 16; o > 0; o >>= 1)
                    contrib += __shfl_xor_sync(0xffffffffu, contrib, o);
                run += contrib;
                pos -= 32;
            }
        }
        if (lane == 0) s_excl = excl;
    }
    __syncthreads();

    int bexcl = s_excl;
    if (i < n) {
        int e = bexcl + sh[t] - c;
        g_rows[i] = e;
        g_cur[i]  = e;
    }
    if (t == 255 && b > 0) {
        g_blk_inc[b] = bexcl + sh[255];
        __threadfence();
        atomicExch(&g_blk_flag[b], 2);
    }
}

// ---------------- CSR fill: 4 edges/thread (MLP=4 on the atomic chain) ---------
__global__ void k_fill(const void* __restrict__ ei, int E) {
    int t = blockIdx.x * blockDim.x + threadIdx.x;
    int e = t * 4;
    if (e >= E) return;
    int s[4], d[4];
    int m = E - e;
    if (g_is64) {
        const long long* ps = (const long long*)ei;
        const long long* pd = ps + E;
        if (m >= 4) {
            longlong2 s0 = ((const longlong2*)(ps + e))[0];
            longlong2 s1 = ((const longlong2*)(ps + e))[1];
            longlong2 d0 = ((const longlong2*)(pd + e))[0];
            longlong2 d1 = ((const longlong2*)(pd + e))[1];
            s[0] = (int)s0.x; s[1] = (int)s0.y; s[2] = (int)s1.x; s[3] = (int)s1.y;
            d[0] = (int)d0.x; d[1] = (int)d0.y; d[2] = (int)d1.x; d[3] = (int)d1.y;
        } else {
            for (int k = 0; k < 4; k++) {
                s[k] = (k < m) ? (int)ps[e + k] : 0;
                d[k] = (k < m) ? (int)pd[e + k] : -1;
            }
        }
    } else {
        const int* ps = (const int*)ei;
        const int* pd = ps + E;
        if (m >= 4) {
            int4 sv = *(const int4*)(ps + e);
            int4 dv = *(const int4*)(pd + e);
            s[0] = sv.x; s[1] = sv.y; s[2] = sv.z; s[3] = sv.w;
            d[0] = dv.x; d[1] = dv.y; d[2] = dv.z; d[3] = dv.w;
        } else {
            for (int k = 0; k < 4; k++) {
                s[k] = (k < m) ? ps[e + k] : 0;
                d[k] = (k < m) ? pd[e + k] : -1;
            }
        }
    }
    int pos[4];
#pragma unroll
    for (int k = 0; k < 4; k++)
        pos[k] = (d[k] >= 0) ? atomicAdd(&g_cur[d[k]], 1) : 0;
#pragma unroll
    for (int k = 0; k < 4; k++)
        if (d[k] >= 0) g_csr[pos[k]] = s[k];
}

// ---------------- layer-1 GEMM: hn = (x @ W1) * dinv -> fp16 -------------------
__global__ void __launch_bounds__(256) k_gemm1(const float* __restrict__ x,
                                               const float* __restrict__ W1,
                                               int n) {
    __shared__ float4 w1t[HID * 128];   // [j][k4], 16B lane stride: conflict-free
    for (int i = threadIdx.x; i < HID * 128; i += 256) {
        int j = i >> 7, k4 = i & 127;
        w1t[i] = make_float4(W1[(4 * k4 + 0) * HID + j],
                             W1[(4 * k4 + 1) * HID + j],
                             W1[(4 * k4 + 2) * HID + j],
                             W1[(4 * k4 + 3) * HID + j]);
    }
    __syncthreads();

    int lane = threadIdx.x & 31;
    int warp = (blockIdx.x * blockDim.x + threadIdx.x) >> 5;
    int nw   = (gridDim.x * blockDim.x) >> 5;

    for (int r0 = warp * 4; r0 < n; r0 += nw * 4) {
        int nr = n - r0 >= 4 ? 4 : n - r0;
        float acc[4][HID];
#pragma unroll
        for (int r = 0; r < 4; r++)
#pragma unroll
            for (int j = 0; j < HID; j++) acc[r][j] = 0.f;

#pragma unroll
        for (int it = 0; it < 4; it++) {
            float4 xv[4];
#pragma unroll
            for (int r = 0; r < 4; r++)
                xv[r] = (r < nr)
                      ? ((const float4*)(x + (size_t)(r0 + r) * IN_FEAT))[it * 32 + lane]
                      : make_float4(0.f, 0.f, 0.f, 0.f);
#pragma unroll
            for (int j = 0; j < HID; j++) {
                float4 w = w1t[j * 128 + it * 32 + lane];
#pragma unroll
                for (int r = 0; r < 4; r++)
                    acc[r][j] += xv[r].x * w.x + xv[r].y * w.y
                               + xv[r].z * w.z + xv[r].w * w.w;
            }
        }

        unsigned long long A[32];
#pragma unroll
        for (int r = 0; r < 4; r++)
#pragma unroll
            for (int p = 0; p < 8; p++)
                A[r * 8 + p] = pack2(acc[r][2 * p], acc[r][2 * p + 1]);

#pragma unroll
        for (int h = 16; h >= 1; h >>= 1) {
            bool up = (lane & h) != 0;
#pragma unroll
            for (int q = 0; q < h; q++) {
                unsigned long long send = up ? A[q] : A[q + h];
                unsigned long long got  = __shfl_xor_sync(0xffffffffu, send, h);
                unsigned long long keep = up ? A[q + h] : A[q];
                A[q] = add2(keep, got);
            }
        }

        int r = lane >> 3, p = lane & 7;
        int row = r0 + r;
        if (row < n) {
            float di = g_dinv[row];
            float2 f = unpack2(A[0]);
            ((__half2*)g_hnh)[(size_t)row * 8 + p] =
                __floats2half2_rn(f.x * di, f.y * di);
        }
    }
}

// ---------------- fused: aggregate1 + bias/relu + GEMM2 -> h2 fp16 -------------
// 2 lanes/node own one 16B half each; edge loop unrolled x4 for MLP.
__global__ void __launch_bounds__(256) k_l1(const float* __restrict__ b1,
                                            const float* __restrict__ W2, int n) {
    __shared__ float w2s[HID * NC];
    __shared__ float b1s[HID];
    if (threadIdx.x < HID * NC) w2s[threadIdx.x] = W2[threadIdx.x];
    if (threadIdx.x < HID)      b1s[threadIdx.x] = b1[threadIdx.x];
    __syncthreads();

    int t = blockIdx.x * blockDim.x + threadIdx.x;
    int valid = t < n * 2;
    int node = valid ? (t >> 1) : 0;     // clamp: keep warp converged for shfl
    int c    = t & 1;

    float a[8];
#pragma unroll
    for (int q = 0; q < 8; q++) a[q] = 0.f;
    add8(a, g_hnh[(size_t)node * 2 + c]);        // self-loop (own half)

    int beg = g_rows[node], cnt = g_cnt[node];
    int j = 0;
    for (; j + 4 <= cnt; j += 4) {
        int s0 = __ldg(&g_csr[beg + j]);
        int s1 = __ldg(&g_csr[beg + j + 1]);
        int s2 = __ldg(&g_csr[beg + j + 2]);
        int s3 = __ldg(&g_csr[beg + j + 3]);
        uint4 v0 = __ldg(&g_hnh[(size_t)s0 * 2 + c]);
        uint4 v1 = __ldg(&g_hnh[(size_t)s1 * 2 + c]);
        uint4 v2 = __ldg(&g_hnh[(size_t)s2 * 2 + c]);
        uint4 v3 = __ldg(&g_hnh[(size_t)s3 * 2 + c]);
        add8(a, v0); add8(a, v1); add8(a, v2); add8(a, v3);
    }
    for (; j < cnt; j++) {
        int s = __ldg(&g_csr[beg + j]);
        add8(a, __ldg(&g_hnh[(size_t)s * 2 + c]));
    }

    float other[8];
#pragma unroll
    for (int q = 0; q < 8; q++)
        other[q] = __shfl_xor_sync(0xffffffffu, a[q], 1);

    if (valid && c == 0) {
        float di = g_dinv[node];
        float h1[HID];
#pragma unroll
        for (int k = 0; k < 8; k++) {
            float v0 = di * a[k] + b1s[k];
            float v1 = di * other[k] + b1s[k + 8];
            h1[k]     = v0 > 0.f ? v0 : 0.f;
            h1[k + 8] = v1 > 0.f ? v1 : 0.f;
        }
        float o[NC];
#pragma unroll
        for (int q = 0; q < NC; q++) o[q] = 0.f;
#pragma unroll
        for (int k = 0; k < HID; k++) {
            float hv = h1[k];
#pragma unroll
            for (int q = 0; q < NC; q++) o[q] += hv * w2s[k * NC + q];
        }
        uint4 st;
        *(__half2*)&st.x = __floats2half2_rn(o[0] * di, o[1] * di);
        *(__half2*)&st.y = __floats2half2_rn(o[2] * di, o[3] * di);
        *(__half2*)&st.z = __floats2half2_rn(o[4] * di, o[5] * di);
        *(__half2*)&st.w = __floats2half2_rn(o[6] * di, 0.f);
        g_h2h[node] = st;
    }
}

// ---------------- fused: aggregate2 + bias + log_softmax -> out ----------------
// 4 lanes/node split the edge list; unrolled x4 for MLP.
__global__ void __launch_bounds__(256) k_l2(const float* __restrict__ b2,
                                            float* __restrict__ outp, int n) {
    __shared__ float b2s[NC];
    if (threadIdx.x < NC) b2s[threadIdx.x] = b2[threadIdx.x];
    __syncthreads();

    int t = blockIdx.x * blockDim.x + threadIdx.x;
    int valid = t < n * 4;
    int node = valid ? (t >> 2) : 0;
    int c    = t & 3;

    float a[8];
#pragma unroll
    for (int q = 0; q < 8; q++) a[q] = 0.f;

    int beg = g_rows[node], cnt = g_cnt[node];
    int j = c;
    for (; j + 12 < cnt; j += 16) {
        int s0 = __ldg(&g_csr[beg + j]);
        int s1 = __ldg(&g_csr[beg + j + 4]);
        int s2 = __ldg(&g_csr[beg + j + 8]);
        int s3 = __ldg(&g_csr[beg + j + 12]);
        uint4 v0 = __ldg(&g_h2h[s0]);
        uint4 v1 = __ldg(&g_h2h[s1]);
        uint4 v2 = __ldg(&g_h2h[s2]);
        uint4 v3 = __ldg(&g_h2h[s3]);
        add8(a, v0); add8(a, v1); add8(a, v2); add8(a, v3);
    }
    for (; j < cnt; j += 4) {
        int s = __ldg(&g_csr[beg + j]);
        add8(a, __ldg(&g_h2h[s]));
    }
#pragma unroll
    for (int off = 1; off <= 2; off <<= 1)
#pragma unroll
        for (int q = 0; q < 8; q++)
            a[q] += __shfl_xor_sync(0xffffffffu, a[q], off);

    if (valid && c == 0) {
        add8(a, g_h2h[node]);                     // self-loop
        float di = g_dinv[node];
        float lg[NC];
        float m = -1e30f;
#pragma unroll
        for (int q = 0; q < NC; q++) {
            lg[q] = di * a[q] + b2s[q];
            m = fmaxf(m, lg[q]);
        }
        float s = 0.f;
#pragma unroll
        for (int q = 0; q < NC; q++) s += expf(lg[q] - m);
        float ls = logf(s) + m;
#pragma unroll
        for (int q = 0; q < NC; q++) outp[(size_t)node * NC + q] = lg[q] - ls;
    }
}

// ---------------- launch -------------------------------------------------------
extern "C" void kernel_launch(void* const* d_in, const int* in_sizes, int n_in,
                              void* d_out, int out_size) {
    const float* x  = (const float*)d_in[0];
    const void*  ei = d_in[1];
    const float* W1 = (const float*)d_in[2];
    const float* b1 = (const float*)d_in[3];
    const float* W2 = (const float*)d_in[4];
    const float* b2 = (const float*)d_in[5];
    float*       out = (float*)d_out;

    int n = in_sizes[0] / IN_FEAT;   // 100000
    int E = in_sizes[1] / 2;         // 3200000

    const int T = 256;
    int nb  = (n + T - 1) / T;                // 391
    int eb4 = (E / 4 + T - 1) / T;            // 3125 (4 edges/thread)
    int l1b = (n * 2 + T - 1) / T;            // 782
    int l2b = (n * 4 + T - 1) / T;            // 1563

    k_zero_detect<<<nb, T>>>((const int*)ei, n);
    k_count      <<<eb4, T>>>(ei, E);
    k_csr_offsets<<<nb, T>>>(n);
    k_fill       <<<eb4, T>>>(ei, E);
    k_gemm1      <<<592, T>>>(x, W1, n);
    k_l1         <<<l1b, T>>>(b1, W2, n);
    k_l2         <<<l2b, T>>>(b2, out, n);
}

// round 12
// speedup vs baseline: 1.5220x; 1.5220x over previous
#include <cuda_runtime.h>
#include <cuda_fp16.h>
#include <math.h>

#define NN 100000
#define NE 3200000
#define IN_FEAT 512
#define HID 16
#define NC 7
#define MAXNB 512   // max node-blocks (ceil(100000/256)=391)

// ---------------- scratch (device globals; no allocation allowed) -------------
__device__ int   g_is64;
__device__ int   g_cnt [NN];      // in-degree (edges only)
__device__ int   g_rows[NN];      // CSR row starts
__device__ int   g_cur [NN];      // fill cursors
__device__ int   g_blk_agg [MAXNB];
__device__ int   g_blk_inc [MAXNB];
__device__ int   g_blk_flag[MAXNB];   // 0=none 1=agg 2=inclusive
__device__ int   g_csr [NE];      // src per CSR slot
__device__ float g_dinv[NN];
__device__ uint4 g_hnh [NN * 2];  // h1*dinv, 16 x fp16 per node (32B)
__device__ uint4 g_h2h [NN];      // h2*dinv, 7 x fp16 + pad (16B)

// ---------------- helpers ------------------------------------------------------
__device__ __forceinline__ unsigned long long pack2(float a, float b) {
    unsigned long long r;
    asm("mov.b64 %0, {%1,%2};" : "=l"(r) : "f"(a), "f"(b));
    return r;
}
__device__ __forceinline__ unsigned long long add2(unsigned long long a,
                                                   unsigned long long b) {
    unsigned long long d;
    asm("add.rn.f32x2 %0, %1, %2;" : "=l"(d) : "l"(a), "l"(b));
    return d;
}
__device__ __forceinline__ float2 unpack2(unsigned long long v) {
    float2 f;
    asm("mov.b64 {%0,%1}, %2;" : "=f"(f.x), "=f"(f.y) : "l"(v));
    return f;
}
__device__ __forceinline__ void add8(float* a, uint4 v) {
    float2 f0 = __half22float2(*(__half2*)&v.x);
    float2 f1 = __half22float2(*(__half2*)&v.y);
    float2 f2 = __half22float2(*(__half2*)&v.z);
    float2 f3 = __half22float2(*(__half2*)&v.w);
    a[0] += f0.x; a[1] += f0.y; a[2] += f1.x; a[3] += f1.y;
    a[4] += f2.x; a[5] += f2.y; a[6] += f3.x; a[7] += f3.y;
}

// ---------------- zero counts + scan flags + dtype detect ----------------------
__global__ void k_zero_detect(const int* __restrict__ ei, int n) {
    int i = blockIdx.x * blockDim.x + threadIdx.x;
    if (i < n) g_cnt[i] = 0;
    if (i < MAXNB) { g_blk_flag[i] = 0; g_blk_agg[i] = 0; g_blk_inc[i] = 0; }
    if (blockIdx.x == 0 && threadIdx.x == 0) {
        int nz = 0;
#pragma unroll
        for (int k = 1; k < 64; k += 2) nz |= ei[k];   // int64 high words == 0
        g_is64 = (nz == 0) ? 1 : 0;
    }
}

// ---------------- degree count (dst half only, 2 edges/thread) -----------------
__global__ void k_count(const void* __restrict__ ei, int E) {
    int t = blockIdx.x * blockDim.x + threadIdx.x;
    int e = t * 2;
    if (e >= E) return;
    if (g_is64) {
        const long long* p = (const long long*)ei + E;
        longlong2 v = ((const longlong2*)p)[t];
        atomicAdd(&g_cnt[(int)v.x], 1);
        if (e + 1 < E) atomicAdd(&g_cnt[(int)v.y], 1);
    } else {
        const int* p = (const int*)ei + E;
        int2 v = ((const int2*)p)[t];
        atomicAdd(&g_cnt[v.x], 1);
        if (e + 1 < E) atomicAdd(&g_cnt[v.y], 1);
    }
}

// ---------------- fused dinv + full exclusive scan (decoupled lookback) --------
__global__ void __launch_bounds__(256) k_csr_offsets(int n) {
    __shared__ int sh[256];
    __shared__ int s_excl;
    int b = blockIdx.x, t = threadIdx.x;
    int i = b * 256 + t;
    int c = (i < n) ? g_cnt[i] : 0;
    if (i < n) g_dinv[i] = rsqrtf((float)(c + 1));

    sh[t] = c;
    __syncthreads();
#pragma unroll
    for (int off = 1; off < 256; off <<= 1) {
        int v = (t >= off) ? sh[t - off] : 0;
        __syncthreads();
        sh[t] += v;
        __syncthreads();
    }

    if (t == 255) {
        if (b == 0) {
            g_blk_inc[0] = sh[255];
            __threadfence();
            atomicExch(&g_blk_flag[0], 2);
        } else {
            g_blk_agg[b] = sh[255];
            __threadfence();
            atomicExch(&g_blk_flag[b], 1);
        }
    }

    if (b == 0) {
        if (t == 0) s_excl = 0;
    } else if (t < 32) {
        int lane = t;
        int run = 0, pos = b - 1, done = 0, excl = 0;
        while (!done) {
            int idx = pos - lane;
            int f = (idx >= 0) ? *(volatile int*)&g_blk_flag[idx] : 2;
            unsigned b2 = __ballot_sync(0xffffffffu, f >= 2);
            unsigned b1 = __ballot_sync(0xffffffffu, f >= 1);
            if (b2) {
                int k = __ffs(b2) - 1;
                unsigned need = (k == 0) ? 0u : ((1u << k) - 1u);
                if ((b1 & need) == need) {
                    int contrib = 0;
                    if (lane < k)       contrib = *(volatile int*)&g_blk_agg[idx];
                    else if (lane == k) contrib = (idx >= 0)
                                                ? *(volatile int*)&g_blk_inc[idx] : 0;
#pragma unroll
                    for (int o = 16; o > 0; o >>= 1)
                        contrib += __shfl_xor_sync(0xffffffffu, contrib, o);
                    excl = run + contrib;
                    done = 1;
                }
            } else if (b1 == 0xffffffffu) {
                int contrib = *(volatile int*)&g_blk_agg[idx];
#pragma unroll
                for (int o = 16; o > 0; o >>= 1)
                    contrib += __shfl_xor_sync(0xffffffffu, contrib, o);
                run += contrib;
                pos -= 32;
            }
        }
        if (lane == 0) s_excl = excl;
    }
    __syncthreads();

    int bexcl = s_excl;
    if (i < n) {
        int e = bexcl + sh[t] - c;
        g_rows[i] = e;
        g_cur[i]  = e;
    }
    if (t == 255 && b > 0) {
        g_blk_inc[b] = bexcl + sh[255];
        __threadfence();
        atomicExch(&g_blk_flag[b], 2);
    }
}

// ---------------- CSR fill (1 edge/thread — proven fastest config) -------------
__global__ void k_fill(const void* __restrict__ ei, int E) {
    int e = blockIdx.x * blockDim.x + threadIdx.x;
    if (e >= E) return;
    int s, d;
    if (g_is64) {
        const long long* p = (const long long*)ei;
        s = (int)p[e]; d = (int)p[(size_t)E + e];
    } else {
        const int* p = (const int*)ei;
        s = p[e]; d = p[(size_t)E + e];
    }
    int pos = atomicAdd(&g_cur[d], 1);
    g_csr[pos] = s;
}

// ---------------- layer-1 GEMM: hn = (x @ W1) * dinv -> fp16 -------------------
__global__ void __launch_bounds__(256) k_gemm1(const float* __restrict__ x,
                                               const float* __restrict__ W1,
                                               int n) {
    __shared__ float4 w1t[HID * 128];   // [j][k4], 16B lane stride: conflict-free
    for (int i = threadIdx.x; i < HID * 128; i += 256) {
        int j = i >> 7, k4 = i & 127;
        w1t[i] = make_float4(W1[(4 * k4 + 0) * HID + j],
                             W1[(4 * k4 + 1) * HID + j],
                             W1[(4 * k4 + 2) * HID + j],
                             W1[(4 * k4 + 3) * HID + j]);
    }
    __syncthreads();

    int lane = threadIdx.x & 31;
    int warp = (blockIdx.x * blockDim.x + threadIdx.x) >> 5;
    int nw   = (gridDim.x * blockDim.x) >> 5;

    for (int r0 = warp * 4; r0 < n; r0 += nw * 4) {
        int nr = n - r0 >= 4 ? 4 : n - r0;
        float acc[4][HID];
#pragma unroll
        for (int r = 0; r < 4; r++)
#pragma unroll
            for (int j = 0; j < HID; j++) acc[r][j] = 0.f;

#pragma unroll
        for (int it = 0; it < 4; it++) {
            float4 xv[4];
#pragma unroll
            for (int r = 0; r < 4; r++)
                xv[r] = (r < nr)
                      ? ((const float4*)(x + (size_t)(r0 + r) * IN_FEAT))[it * 32 + lane]
                      : make_float4(0.f, 0.f, 0.f, 0.f);
#pragma unroll
            for (int j = 0; j < HID; j++) {
                float4 w = w1t[j * 128 + it * 32 + lane];
#pragma unroll
                for (int r = 0; r < 4; r++)
                    acc[r][j] += xv[r].x * w.x + xv[r].y * w.y
                               + xv[r].z * w.z + xv[r].w * w.w;
            }
        }

        unsigned long long A[32];
#pragma unroll
        for (int r = 0; r < 4; r++)
#pragma unroll
            for (int p = 0; p < 8; p++)
                A[r * 8 + p] = pack2(acc[r][2 * p], acc[r][2 * p + 1]);

#pragma unroll
        for (int h = 16; h >= 1; h >>= 1) {
            bool up = (lane & h) != 0;
#pragma unroll
            for (int q = 0; q < h; q++) {
                unsigned long long send = up ? A[q] : A[q + h];
                unsigned long long got  = __shfl_xor_sync(0xffffffffu, send, h);
                unsigned long long keep = up ? A[q + h] : A[q];
                A[q] = add2(keep, got);
            }
        }

        int r = lane >> 3, p = lane & 7;
        int row = r0 + r;
        if (row < n) {
            float di = g_dinv[row];
            float2 f = unpack2(A[0]);
            ((__half2*)g_hnh)[(size_t)row * 8 + p] =
                __floats2half2_rn(f.x * di, f.y * di);
        }
    }
}

// ---------------- fused: aggregate1 + bias/relu + GEMM2 -> h2 fp16 -------------
// Column-paired: 2 lanes/node, each owns one 16B half; loads coalesce per edge.
__global__ void __launch_bounds__(256) k_l1(const float* __restrict__ b1,
                                            const float* __restrict__ W2, int n) {
    __shared__ float w2s[HID * NC];
    __shared__ float b1s[HID];
    if (threadIdx.x < HID * NC) w2s[threadIdx.x] = W2[threadIdx.x];
    if (threadIdx.x < HID)      b1s[threadIdx.x] = b1[threadIdx.x];
    __syncthreads();

    int t = blockIdx.x * blockDim.x + threadIdx.x;
    int valid = t < n * 2;
    int node = valid ? (t >> 1) : 0;     // clamp: keep warp converged for shfl
    int c    = t & 1;

    float a[8];
#pragma unroll
    for (int q = 0; q < 8; q++) a[q] = 0.f;
    add8(a, g_hnh[(size_t)node * 2 + c]);        // self-loop (own half)

    int beg = g_rows[node], cnt = g_cnt[node];
    int j = 0;
    for (; j + 2 <= cnt; j += 2) {
        int s0 = __ldg(&g_csr[beg + j]);
        int s1 = __ldg(&g_csr[beg + j + 1]);
        uint4 v0 = __ldg(&g_hnh[(size_t)s0 * 2 + c]);
        uint4 v1 = __ldg(&g_hnh[(size_t)s1 * 2 + c]);
        add8(a, v0); add8(a, v1);
    }
    if (j < cnt) {
        int s = __ldg(&g_csr[beg + j]);
        add8(a, __ldg(&g_hnh[(size_t)s * 2 + c]));
    }

    // exchange halves within the pair
    float other[8];
#pragma unroll
    for (int q = 0; q < 8; q++)
        other[q] = __shfl_xor_sync(0xffffffffu, a[q], 1);

    if (valid && c == 0) {
        float di = g_dinv[node];
        float h1[HID];
#pragma unroll
        for (int k = 0; k < 8; k++) {
            float v0 = di * a[k] + b1s[k];
            float v1 = di * other[k] + b1s[k + 8];
            h1[k]     = v0 > 0.f ? v0 : 0.f;
            h1[k + 8] = v1 > 0.f ? v1 : 0.f;
        }
        float o[NC];
#pragma unroll
        for (int q = 0; q < NC; q++) o[q] = 0.f;
#pragma unroll
        for (int k = 0; k < HID; k++) {
            float hv = h1[k];
#pragma unroll
            for (int q = 0; q < NC; q++) o[q] += hv * w2s[k * NC + q];
        }
        uint4 st;
        *(__half2*)&st.x = __floats2half2_rn(o[0] * di, o[1] * di);
        *(__half2*)&st.y = __floats2half2_rn(o[2] * di, o[3] * di);
        *(__half2*)&st.z = __floats2half2_rn(o[4] * di, o[5] * di);
        *(__half2*)&st.w = __floats2half2_rn(o[6] * di, 0.f);
        g_h2h[node] = st;
    }
}

// ---------------- fused: aggregate2 + bias + log_softmax -> out ----------------
// 4 lanes/node split the edge list (csr reads coalesce 16B per quad).
__global__ void __launch_bounds__(256) k_l2(const float* __restrict__ b2,
                                            float* __restrict__ outp, int n) {
    __shared__ float b2s[NC];
    if (threadIdx.x < NC) b2s[threadIdx.x] = b2[threadIdx.x];
    __syncthreads();

    int t = blockIdx.x * blockDim.x + threadIdx.x;
    int valid = t < n * 4;
    int node = valid ? (t >> 2) : 0;
    int c    = t & 3;

    float a[8];
#pragma unroll
    for (int q = 0; q < 8; q++) a[q] = 0.f;

    int beg = g_rows[node], cnt = g_cnt[node];
#pragma unroll 2
    for (int j = c; j < cnt; j += 4) {
        int s = __ldg(&g_csr[beg + j]);
        add8(a, __ldg(&g_h2h[s]));
    }
#pragma unroll
    for (int off = 1; off <= 2; off <<= 1)
#pragma unroll
        for (int q = 0; q < 8; q++)
            a[q] += __shfl_xor_sync(0xffffffffu, a[q], off);

    if (valid && c == 0) {
        add8(a, g_h2h[node]);                     // self-loop
        float di = g_dinv[node];
        float lg[NC];
        float m = -1e30f;
#pragma unroll
        for (int q = 0; q < NC; q++) {
            lg[q] = di * a[q] + b2s[q];
            m = fmaxf(m, lg[q]);
        }
        float s = 0.f;
#pragma unroll
        for (int q = 0; q < NC; q++) s += expf(lg[q] - m);
        float ls = logf(s) + m;
#pragma unroll
        for (int q = 0; q < NC; q++) outp[(size_t)node * NC + q] = lg[q] - ls;
    }
}

// ---------------- launch: fork gemm1 || fill (complementary pipes) -------------
extern "C" void kernel_launch(void* const* d_in, const int* in_sizes, int n_in,
                              void* d_out, int out_size) {
    const float* x  = (const float*)d_in[0];
    const void*  ei = d_in[1];
    const float* W1 = (const float*)d_in[2];
    const float* b1 = (const float*)d_in[3];
    const float* W2 = (const float*)d_in[4];
    const float* b2 = (const float*)d_in[5];
    float*       out = (float*)d_out;

    int n = in_sizes[0] / IN_FEAT;   // 100000
    int E = in_sizes[1] / 2;         // 3200000

    const int T = 256;
    int nb  = (n + T - 1) / T;            // 391
    int eb  = (E + T - 1) / T;            // 12500
    int eb2 = (E / 2 + T - 1) / T;        // 6250
    int l1b = (n * 2 + T - 1) / T;        // 782
    int l2b = (n * 4 + T - 1) / T;        // 1563

    // side stream + events (kernel_launch runs only twice: correctness + capture;
    // not freeing them leaks 2 streams/2 events total — host-side, allowed)
    cudaStream_t s2;
    cudaEvent_t ev_fork, ev_join;
    cudaStreamCreateWithFlags(&s2, cudaStreamNonBlocking);
    cudaEventCreateWithFlags(&ev_fork, cudaEventDisableTiming);
    cudaEventCreateWithFlags(&ev_join, cudaEventDisableTiming);

    k_zero_detect<<<nb, T>>>((const int*)ei, n);
    k_count      <<<eb2, T>>>(ei, E);
    k_csr_offsets<<<nb, T>>>(n);          // produces g_dinv + row starts

    // fork: gemm1 (FMA/DRAM-bound) runs on s2 concurrent with fill (latency-bound)
    cudaEventRecord(ev_fork, 0);
    cudaStreamWaitEvent(s2, ev_fork, 0);
    k_gemm1<<<592, T, 0, s2>>>(x, W1, n);
    cudaEventRecord(ev_join, s2);

    k_fill<<<eb, T>>>(ei, E);             // main stream, overlaps gemm1

    cudaStreamWaitEvent(0, ev_join, 0);   // join before consumers
    k_l1<<<l1b, T>>>(b1, W2, n);
    k_l2<<<l2b, T>>>(b2, out, n);
}